// round 10
// baseline (speedup 1.0000x reference)
#include <cuda_runtime.h>
#include <cstdint>

#define DIMS    64
#define HID     64
#define NMLP    63
#define TILE_B  128
#define NTILES  256
#define THREADS 256

// Scratch: fragment-major, tf32-rounded, mask-baked weights, PAIRED layout.
// Per r: [p][nt][lane] float4 with p=pair of k-blocks (2p,2p+1):
//   ( W[2p*8+qc][n], W[2p*8+qc+4][n], W[(2p+1)*8+qc][n], W[(2p+1)*8+qc+4][n] ),  n = nt*8+qr
__device__ float g_w1f[NMLP][4096];
__device__ float g_w2f[NMLP][4096];
__device__ float g_o0d;

__device__ __forceinline__ float to_tf32(float x) {
    uint32_t u;
    asm("cvt.rna.tf32.f32 %0, %1;" : "=r"(u) : "f"(x));
    return __uint_as_float(u);
}

// ---------------- Preprocess: mask + tf32 + paired fragment relayout ----------------
__global__ void prep_kernel(const float* __restrict__ W1, const float* __restrict__ W2,
                            const float* __restrict__ w01, const float* __restrict__ b01,
                            const float* __restrict__ w02, const float* __restrict__ b02,
                            const float* __restrict__ w03, const float* __restrict__ b03) {
    __shared__ float sw[4096];
    const int r = blockIdx.x, tid = threadIdx.x;

    for (int i = tid; i < 4096; i += THREADS) sw[i] = W1[r * 4096 + i];
    __syncthreads();
    for (int e = tid; e < 1024; e += THREADS) {      // e = float4 index
        int lane = e & 31, nt = (e >> 5) & 7, p = e >> 8;
        int qr = lane >> 2, qc = lane & 3;
        int n = nt * 8 + qr;
        int ka = 2 * p * 8 + qc, kb = (2 * p + 1) * 8 + qc;
        float4 v;
        v.x = (ka     <= r) ? to_tf32(sw[ka * 64 + n])       : 0.f;
        v.y = (ka + 4 <= r) ? to_tf32(sw[(ka + 4) * 64 + n]) : 0.f;
        v.z = (kb     <= r) ? to_tf32(sw[kb * 64 + n])       : 0.f;
        v.w = (kb + 4 <= r) ? to_tf32(sw[(kb + 4) * 64 + n]) : 0.f;
        ((float4*)g_w1f[r])[e] = v;
    }
    __syncthreads();
    for (int i = tid; i < 4096; i += THREADS) sw[i] = W2[r * 4096 + i];
    __syncthreads();
    for (int e = tid; e < 1024; e += THREADS) {
        int lane = e & 31, nt = (e >> 5) & 7, p = e >> 8;
        int qr = lane >> 2, qc = lane & 3;
        int n = nt * 8 + qr;
        int ka = 2 * p * 8 + qc, kb = (2 * p + 1) * 8 + qc;
        float4 v;
        v.x = to_tf32(sw[ka * 64 + n]);
        v.y = to_tf32(sw[(ka + 4) * 64 + n]);
        v.z = to_tf32(sw[kb * 64 + n]);
        v.w = to_tf32(sw[(kb + 4) * 64 + n]);
        ((float4*)g_w2f[r])[e] = v;
    }
    if (r == 0) {   // dim-0 constant MLP, once for the whole grid
        __syncthreads();
        if (tid < 64) {
            float acc = b01[tid];
            #pragma unroll
            for (int k = 0; k < 10; k++) {
                float v = (float)(0.1 * (-5.0 + 10.0 * (double)k / 9.0));
                acc += v * w01[k * 64 + tid];
            }
            sw[tid] = fmaxf(acc, 0.f);
        }
        __syncthreads();
        if (tid < 64) {
            float acc = b02[tid];
            #pragma unroll 8
            for (int k = 0; k < 64; k++) acc += sw[k] * w02[k * 64 + tid];
            sw[64 + tid] = fmaxf(acc, 0.f);
        }
        __syncthreads();
        if (tid == 0) {
            float acc = b03[0];
            #pragma unroll 8
            for (int k = 0; k < 64; k++) acc += sw[64 + k] * w03[k];
            g_o0d = acc;
        }
    }
}

// ---------------- Main kernel ----------------
// smem: w1buf[2][4096] | w2buf[2][4096] | bias[2][192] | Xfrag[8warp][8kb][32lane]float4
#define SM_W1   0
#define SM_W2   8192
#define SM_BS   16384
#define SM_X    16768
#define SMEM_FLOATS (16768 + 8192)
#define SMEM_BYTES  (SMEM_FLOATS * 4)

__device__ __forceinline__ void mma8(float* c, const uint32_t* a, float b0, float b1) {
    asm volatile(
        "mma.sync.aligned.m16n8k8.row.col.f32.tf32.tf32.f32 "
        "{%0,%1,%2,%3},{%4,%5,%6,%7},{%8,%9},{%0,%1,%2,%3};"
        : "+f"(c[0]), "+f"(c[1]), "+f"(c[2]), "+f"(c[3])
        : "r"(a[0]), "r"(a[1]), "r"(a[2]), "r"(a[3]),
          "r"(__float_as_uint(b0)), "r"(__float_as_uint(b1)));
}

__global__ __launch_bounds__(THREADS, 2)
void mlplist_kernel(const float* __restrict__ inputs,
                    const float* __restrict__ b1g, const float* __restrict__ b2g,
                    const float* __restrict__ W3g, const float* __restrict__ b3g,
                    float* __restrict__ out) {
    extern __shared__ float sm[];
    const int tid = threadIdx.x, bx = blockIdx.x;
    const int warp = tid >> 5, lane = tid & 31;
    const int qr = lane >> 2, qc = lane & 3;
    const int rowbase = bx * TILE_B + warp * 16;

    auto issue_r = [&](int rn, int st) {
        {   // W1 fragments: only the pair-blocks actually used
            int nf4 = (((rn >> 3) + 2) >> 1) * 256;     // float4 chunks
            float* d = sm + SM_W1 + st * 4096;
            const float* s = g_w1f[rn];
            for (int c = tid; c < nf4; c += THREADS) {
                uint32_t da = (uint32_t)__cvta_generic_to_shared(d + c * 4);
                asm volatile("cp.async.cg.shared.global [%0], [%1], 16;" :: "r"(da), "l"(s + c * 4));
            }
        }
        {   // W2 fragments: full 16KB
            float* d = sm + SM_W2 + st * 4096;
            const float* s = g_w2f[rn];
            #pragma unroll
            for (int it = 0; it < 4; it++) {
                int c = tid + it * THREADS;
                uint32_t da = (uint32_t)__cvta_generic_to_shared(d + c * 4);
                asm volatile("cp.async.cg.shared.global [%0], [%1], 16;" :: "r"(da), "l"(s + c * 4));
            }
        }
        if (tid < 48) {   // b1 | b2 | w3
            const float* s = (tid < 16) ? (b1g + rn * 64 + tid * 4)
                           : (tid < 32) ? (b2g + rn * 64 + (tid - 16) * 4)
                                        : (W3g + rn * 64 + (tid - 32) * 4);
            float* d = sm + SM_BS + st * 192 + tid * 4;
            uint32_t da = (uint32_t)__cvta_generic_to_shared(d);
            asm volatile("cp.async.cg.shared.global [%0], [%1], 16;" :: "r"(da), "l"(s));
        }
        asm volatile("cp.async.commit_group;" ::: "memory");
    };

    // ---- Prologue: X fragments -> smem, fragment-major per warp ----
    {
        const float* xb = inputs + (size_t)rowbase * 64;
        float4* xs = (float4*)(sm + SM_X) + warp * 256 + lane;
        #pragma unroll
        for (int kb = 0; kb < 8; kb++) {
            int c0 = kb * 8 + qc;
            float4 v;
            v.x = to_tf32(xb[qr * 64 + c0]);
            v.y = to_tf32(xb[(qr + 8) * 64 + c0]);
            v.z = to_tf32(xb[qr * 64 + c0 + 4]);
            v.w = to_tf32(xb[(qr + 8) * 64 + c0 + 4]);
            xs[kb * 32] = v;
        }
    }
    issue_r(0, 0);

    // column 0 (constant dim-0 MLP output)
    {
        float o0 = g_o0d;
        if (tid < TILE_B) out[(size_t)(bx * TILE_B + tid) * 64] = o0;
    }

    const int src0 = (lane & ~3) | (qc >> 1);
    const int src1 = src0 + 2;
    const bool odd = qc & 1;
    const float4* xap = (const float4*)(sm + SM_X) + warp * 256 + lane;

    for (int r = 0; r < NMLP; r++) {
        const int st = r & 1;
        __syncthreads();                       // all warps done with stage st^1 (iter r-1)
        if (r + 1 < NMLP) {
            issue_r(r + 1, st ^ 1);
            asm volatile("cp.async.wait_group 1;" ::: "memory");
        } else {
            asm volatile("cp.async.wait_group 0;" ::: "memory");
        }
        __syncthreads();                       // stage st visible to all warps

        const float4* w1p = (const float4*)(sm + SM_W1 + st * 4096) + lane;
        const float4* w2p = (const float4*)(sm + SM_W2 + st * 4096) + lane;
        const float* bs = sm + SM_BS + st * 192;
        const float b3v = __ldg(b3g + r);
        const int pl = ((r >> 3) + 2) >> 1;    // pair-blocks used

        // ---- GEMM1 (X smem-frags * W1 paired frags) + epilogue + shfl transpose -> a2 ----
        uint32_t a2[8][4];
        #pragma unroll
        for (int ntg = 0; ntg < 8; ntg += 4) {
            float c1[4][4];
            #pragma unroll
            for (int i = 0; i < 4; i++)
                #pragma unroll
                for (int j = 0; j < 4; j++) c1[i][j] = 0.f;
            #pragma unroll 4
            for (int p = 0; p < pl; p++) {
                float4 x0 = xap[(2 * p) * 32];
                float4 x1 = xap[(2 * p + 1) * 32];
                #pragma unroll
                for (int i = 0; i < 4; i++) {
                    float4 b = w1p[(p * 8 + ntg + i) * 32];
                    mma8(c1[i], (const uint32_t*)&x0, b.x, b.y);
                    mma8(c1[i], (const uint32_t*)&x1, b.z, b.w);
                }
            }
            #pragma unroll
            for (int i = 0; i < 4; i++) {
                int nt = ntg + i;
                float2 bb = *(const float2*)(bs + nt * 8 + 2 * qc);
                float v0 = to_tf32(fmaxf(c1[i][0] + bb.x, 0.f));
                float v1 = to_tf32(fmaxf(c1[i][1] + bb.y, 0.f));
                float v2 = to_tf32(fmaxf(c1[i][2] + bb.x, 0.f));
                float v3 = to_tf32(fmaxf(c1[i][3] + bb.y, 0.f));
                // c-layout (g,2t),(g,2t+1),(g+8,2t),(g+8,2t+1) -> a-layout (g,t),(g+8,t),(g,t+4),(g+8,t+4)
                float t0 = __shfl_sync(~0u, v0, src0), t1 = __shfl_sync(~0u, v1, src0);
                float t2 = __shfl_sync(~0u, v2, src0), t3 = __shfl_sync(~0u, v3, src0);
                float u0 = __shfl_sync(~0u, v0, src1), u1 = __shfl_sync(~0u, v1, src1);
                float u2 = __shfl_sync(~0u, v2, src1), u3 = __shfl_sync(~0u, v3, src1);
                a2[nt][0] = __float_as_uint(odd ? t1 : t0);
                a2[nt][1] = __float_as_uint(odd ? t3 : t2);
                a2[nt][2] = __float_as_uint(odd ? u1 : u0);
                a2[nt][3] = __float_as_uint(odd ? u3 : u2);
            }
        }

        // ---- GEMM2 (a2 * W2 paired frags) + fused GEMM3 dot ----
        float p0 = 0.f, p1 = 0.f;
        #pragma unroll
        for (int ntg = 0; ntg < 8; ntg += 4) {
            float c2[4][4];
            #pragma unroll
            for (int i = 0; i < 4; i++)
                #pragma unroll
                for (int j = 0; j < 4; j++) c2[i][j] = 0.f;
            #pragma unroll
            for (int p = 0; p < 4; p++) {
                #pragma unroll
                for (int i = 0; i < 4; i++) {
                    float4 b = w2p[(p * 8 + ntg + i) * 32];
                    mma8(c2[i], a2[2 * p], b.x, b.y);
                    mma8(c2[i], a2[2 * p + 1], b.z, b.w);
                }
            }
            #pragma unroll
            for (int i = 0; i < 4; i++) {
                int nt = ntg + i;
                float2 bb = *(const float2*)(bs + 64 + nt * 8 + 2 * qc);
                float2 ww = *(const float2*)(bs + 128 + nt * 8 + 2 * qc);
                p0 += fmaxf(c2[i][0] + bb.x, 0.f) * ww.x + fmaxf(c2[i][1] + bb.y, 0.f) * ww.y;
                p1 += fmaxf(c2[i][2] + bb.x, 0.f) * ww.x + fmaxf(c2[i][3] + bb.y, 0.f) * ww.y;
            }
        }
        p0 += __shfl_xor_sync(~0u, p0, 1);  p0 += __shfl_xor_sync(~0u, p0, 2);
        p1 += __shfl_xor_sync(~0u, p1, 1);  p1 += __shfl_xor_sync(~0u, p1, 2);
        if (qc == 0) {
            out[(size_t)(rowbase + qr) * 64 + r + 1]     = p0 + b3v;
            out[(size_t)(rowbase + qr + 8) * 64 + r + 1] = p1 + b3v;
        }
    }
}

extern "C" void kernel_launch(void* const* d_in, const int* in_sizes, int n_in,
                              void* d_out, int out_size) {
    const float* inputs = (const float*)d_in[0];
    const float* W1  = (const float*)d_in[1];
    const float* b1  = (const float*)d_in[2];
    const float* W2  = (const float*)d_in[3];
    const float* b2  = (const float*)d_in[4];
    const float* W3  = (const float*)d_in[5];
    const float* b3  = (const float*)d_in[6];
    const float* w01 = (const float*)d_in[7];
    const float* b01 = (const float*)d_in[8];
    const float* w02 = (const float*)d_in[9];
    const float* b02 = (const float*)d_in[10];
    const float* w03 = (const float*)d_in[11];
    const float* b03 = (const float*)d_in[12];
    float* out = (float*)d_out;

    prep_kernel<<<NMLP, THREADS>>>(W1, W2, w01, b01, w02, b02, w03, b03);

    cudaFuncSetAttribute(mlplist_kernel,
                         cudaFuncAttributeMaxDynamicSharedMemorySize, SMEM_BYTES);
    mlplist_kernel<<<NTILES, THREADS, SMEM_BYTES>>>(
        inputs, b1, b2, W3, b3, out);
}

// round 17
// speedup vs baseline: 1.0619x; 1.0619x over previous
#include <cuda_runtime.h>
#include <cstdint>

#define DIMS    64
#define HID     64
#define NMLP    63
#define TILE_B  128
#define NTILES  256
#define THREADS 256

// Scratch: fragment-major, tf32-rounded, mask-baked weights.
// Layout per r: [kb][nt][lane] float2 = (W[kb*8+qc][n], W[kb*8+qc+4][n]),  n = nt*8+qr
__device__ float g_w1f[NMLP][4096];
__device__ float g_w2f[NMLP][4096];
__device__ float g_o0d;

__device__ __forceinline__ float to_tf32(float x) {
    uint32_t u;
    asm("cvt.rna.tf32.f32 %0, %1;" : "=r"(u) : "f"(x));
    return __uint_as_float(u);
}

// ---------------- Preprocess: mask + tf32 + fragment-major relayout ----------------
__global__ void prep_kernel(const float* __restrict__ W1, const float* __restrict__ W2,
                            const float* __restrict__ w01, const float* __restrict__ b01,
                            const float* __restrict__ w02, const float* __restrict__ b02,
                            const float* __restrict__ w03, const float* __restrict__ b03) {
    __shared__ float sw[4096];
    const int r = blockIdx.x, tid = threadIdx.x;

    for (int i = tid; i < 4096; i += THREADS) sw[i] = W1[r * 4096 + i];
    __syncthreads();
    for (int e = tid; e < 2048; e += THREADS) {
        int lane = e & 31, nt = (e >> 5) & 7, kb = e >> 8;
        int qr = lane >> 2, qc = lane & 3;
        int k0 = kb * 8 + qc, n = nt * 8 + qr;
        g_w1f[r][2 * e]     = (k0     <= r) ? to_tf32(sw[k0 * 64 + n])       : 0.f;
        g_w1f[r][2 * e + 1] = (k0 + 4 <= r) ? to_tf32(sw[(k0 + 4) * 64 + n]) : 0.f;
    }
    __syncthreads();
    for (int i = tid; i < 4096; i += THREADS) sw[i] = W2[r * 4096 + i];
    __syncthreads();
    for (int e = tid; e < 2048; e += THREADS) {
        int lane = e & 31, nt = (e >> 5) & 7, kb = e >> 8;
        int qr = lane >> 2, qc = lane & 3;
        int k0 = kb * 8 + qc, n = nt * 8 + qr;
        g_w2f[r][2 * e]     = to_tf32(sw[k0 * 64 + n]);
        g_w2f[r][2 * e + 1] = to_tf32(sw[(k0 + 4) * 64 + n]);
    }
    if (r == 0) {   // dim-0 constant MLP, once for the whole grid
        __syncthreads();
        if (tid < 64) {
            float acc = b01[tid];
            #pragma unroll
            for (int k = 0; k < 10; k++) {
                float v = (float)(0.1 * (-5.0 + 10.0 * (double)k / 9.0));
                acc += v * w01[k * 64 + tid];
            }
            sw[tid] = fmaxf(acc, 0.f);
        }
        __syncthreads();
        if (tid < 64) {
            float acc = b02[tid];
            #pragma unroll 8
            for (int k = 0; k < 64; k++) acc += sw[k] * w02[k * 64 + tid];
            sw[64 + tid] = fmaxf(acc, 0.f);
        }
        __syncthreads();
        if (tid == 0) {
            float acc = b03[0];
            #pragma unroll 8
            for (int k = 0; k < 64; k++) acc += sw[64 + k] * w03[k];
            g_o0d = acc;
        }
    }
}

// ---------------- Main kernel ----------------
// smem: w1buf[2][4096] | w2buf[2][4096] | biasbuf[2][192] (b1|b2|w3)
#define SM_W1   0
#define SM_W2   8192
#define SM_BS   16384
#define SMEM_FLOATS (16384 + 384)
#define SMEM_BYTES  (SMEM_FLOATS * 4)

__device__ __forceinline__ void mma8(float* c, const uint32_t* a, uint32_t b0, uint32_t b1) {
    asm volatile(
        "mma.sync.aligned.m16n8k8.row.col.f32.tf32.tf32.f32 "
        "{%0,%1,%2,%3},{%4,%5,%6,%7},{%8,%9},{%0,%1,%2,%3};"
        : "+f"(c[0]), "+f"(c[1]), "+f"(c[2]), "+f"(c[3])
        : "r"(a[0]), "r"(a[1]), "r"(a[2]), "r"(a[3]), "r"(b0), "r"(b1));
}

__global__ __launch_bounds__(THREADS, 2)
void mlplist_kernel(const float* __restrict__ inputs,
                    const float* __restrict__ b1g, const float* __restrict__ b2g,
                    const float* __restrict__ W3g, const float* __restrict__ b3g,
                    float* __restrict__ out) {
    extern __shared__ float sm[];
    const int tid = threadIdx.x, bx = blockIdx.x;
    const int warp = tid >> 5, lane = tid & 31;
    const int qr = lane >> 2, qc = lane & 3;
    const int rowbase = bx * TILE_B + warp * 16;

    auto issue_r = [&](int rn, int st) {
        {   // W1 fragments: only the kblocks actually used
            int n16 = ((rn >> 3) + 1) * 128;          // 16B chunks
            float* d = sm + SM_W1 + st * 4096;
            const float* s = g_w1f[rn];
            for (int c = tid; c < n16; c += THREADS) {
                uint32_t da = (uint32_t)__cvta_generic_to_shared(d + c * 4);
                asm volatile("cp.async.cg.shared.global [%0], [%1], 16;" :: "r"(da), "l"(s + c * 4));
            }
        }
        {   // W2 fragments: full 16KB
            float* d = sm + SM_W2 + st * 4096;
            const float* s = g_w2f[rn];
            #pragma unroll
            for (int it = 0; it < 4; it++) {
                int c = tid + it * THREADS;
                uint32_t da = (uint32_t)__cvta_generic_to_shared(d + c * 4);
                asm volatile("cp.async.cg.shared.global [%0], [%1], 16;" :: "r"(da), "l"(s + c * 4));
            }
        }
        if (tid < 48) {   // b1 | b2 | w3
            const float* s = (tid < 16) ? (b1g + rn * 64 + tid * 4)
                           : (tid < 32) ? (b2g + rn * 64 + (tid - 16) * 4)
                                        : (W3g + rn * 64 + (tid - 32) * 4);
            float* d = sm + SM_BS + st * 192 + tid * 4;
            uint32_t da = (uint32_t)__cvta_generic_to_shared(d);
            asm volatile("cp.async.cg.shared.global [%0], [%1], 16;" :: "r"(da), "l"(s));
        }
        asm volatile("cp.async.commit_group;" ::: "memory");
    };

    // ---- Prologue: X fragments into registers (loaded once, reused 63x) ----
    uint32_t xa[8][4];
    {
        const float* xb = inputs + (size_t)rowbase * 64;
        #pragma unroll
        for (int kb = 0; kb < 8; kb++) {
            int c0 = kb * 8 + qc;
            xa[kb][0] = __float_as_uint(to_tf32(xb[qr * 64 + c0]));
            xa[kb][1] = __float_as_uint(to_tf32(xb[(qr + 8) * 64 + c0]));
            xa[kb][2] = __float_as_uint(to_tf32(xb[qr * 64 + c0 + 4]));
            xa[kb][3] = __float_as_uint(to_tf32(xb[(qr + 8) * 64 + c0 + 4]));
        }
    }
    issue_r(0, 0);

    // column 0 (constant dim-0 MLP output)
    {
        float o0 = g_o0d;
        if (tid < TILE_B) out[(size_t)(bx * TILE_B + tid) * 64] = o0;
    }

    const int src0 = (lane & ~3) | (qc >> 1);
    const int src1 = src0 + 2;
    const bool odd = qc & 1;

    for (int r = 0; r < NMLP; r++) {
        const int st = r & 1;
        __syncthreads();                       // all warps done with stage st^1 (iter r-1)
        if (r + 1 < NMLP) {
            issue_r(r + 1, st ^ 1);
            asm volatile("cp.async.wait_group 1;" ::: "memory");
        } else {
            asm volatile("cp.async.wait_group 0;" ::: "memory");
        }
        __syncthreads();                       // stage st visible to all warps

        const float2* w1p = (const float2*)(sm + SM_W1 + st * 4096) + lane;
        const float2* w2p = (const float2*)(sm + SM_W2 + st * 4096) + lane;
        const float* bs = sm + SM_BS + st * 192;
        const float b3v = __ldg(b3g + r);
        const int kbl = (r >> 3) + 1;

        // Full-N GEMM2 accumulators persist across both ntg passes (32 regs)
        float c2[8][4];
        #pragma unroll
        for (int i = 0; i < 8; i++)
            #pragma unroll
            for (int j = 0; j < 4; j++) c2[i][j] = 0.f;

        // ---- Interleaved: GEMM1 half -> transpose -> GEMM2 partial ----
        #pragma unroll
        for (int ntg = 0; ntg < 8; ntg += 4) {
            float c1[4][4];
            #pragma unroll
            for (int i = 0; i < 4; i++)
                #pragma unroll
                for (int j = 0; j < 4; j++) c1[i][j] = 0.f;
            for (int kb = 0; kb < kbl; kb++) {
                #pragma unroll
                for (int i = 0; i < 4; i++) {
                    float2 b = w1p[(kb * 8 + ntg + i) * 32];
                    mma8(c1[i], xa[kb], __float_as_uint(b.x), __float_as_uint(b.y));
                }
            }
            // epilogue + in-warp transpose: h1 cols ntg..ntg+3 -> a2 half (16 regs)
            uint32_t a2h[4][4];
            #pragma unroll
            for (int i = 0; i < 4; i++) {
                int nt = ntg + i;
                float2 bb = *(const float2*)(bs + nt * 8 + 2 * qc);
                float v0 = to_tf32(fmaxf(c1[i][0] + bb.x, 0.f));
                float v1 = to_tf32(fmaxf(c1[i][1] + bb.y, 0.f));
                float v2 = to_tf32(fmaxf(c1[i][2] + bb.x, 0.f));
                float v3 = to_tf32(fmaxf(c1[i][3] + bb.y, 0.f));
                // c-layout (g,2t),(g,2t+1),(g+8,2t),(g+8,2t+1) -> a-layout (g,t),(g+8,t),(g,t+4),(g+8,t+4)
                float t0 = __shfl_sync(~0u, v0, src0), t1 = __shfl_sync(~0u, v1, src0);
                float t2 = __shfl_sync(~0u, v2, src0), t3 = __shfl_sync(~0u, v3, src0);
                float u0 = __shfl_sync(~0u, v0, src1), u1 = __shfl_sync(~0u, v1, src1);
                float u2 = __shfl_sync(~0u, v2, src1), u3 = __shfl_sync(~0u, v3, src1);
                a2h[i][0] = __float_as_uint(odd ? t1 : t0);
                a2h[i][1] = __float_as_uint(odd ? t3 : t2);
                a2h[i][2] = __float_as_uint(odd ? u1 : u0);
                a2h[i][3] = __float_as_uint(odd ? u3 : u2);
            }
            // GEMM2 partial over k-blocks ntg..ntg+3, all 8 n-tiles
            #pragma unroll
            for (int i = 0; i < 4; i++) {
                int kb2 = ntg + i;
                #pragma unroll
                for (int nt2 = 0; nt2 < 8; nt2++) {
                    float2 b = w2p[(kb2 * 8 + nt2) * 32];
                    mma8(c2[nt2], a2h[i], __float_as_uint(b.x), __float_as_uint(b.y));
                }
            }
        }

        // ---- fused GEMM3 epilogue: o = relu(h2 + b2) . w3 + b3 ----
        float p0 = 0.f, p1 = 0.f;
        #pragma unroll
        for (int nt = 0; nt < 8; nt++) {
            int col0 = nt * 8 + 2 * qc;
            float2 bb = *(const float2*)(bs + 64 + col0);
            float2 ww = *(const float2*)(bs + 128 + col0);
            p0 += fmaxf(c2[nt][0] + bb.x, 0.f) * ww.x + fmaxf(c2[nt][1] + bb.y, 0.f) * ww.y;
            p1 += fmaxf(c2[nt][2] + bb.x, 0.f) * ww.x + fmaxf(c2[nt][3] + bb.y, 0.f) * ww.y;
        }
        p0 += __shfl_xor_sync(~0u, p0, 1);  p0 += __shfl_xor_sync(~0u, p0, 2);
        p1 += __shfl_xor_sync(~0u, p1, 1);  p1 += __shfl_xor_sync(~0u, p1, 2);
        if (qc == 0) {
            out[(size_t)(rowbase + qr) * 64 + r + 1]     = p0 + b3v;
            out[(size_t)(rowbase + qr + 8) * 64 + r + 1] = p1 + b3v;
        }
    }
}

extern "C" void kernel_launch(void* const* d_in, const int* in_sizes, int n_in,
                              void* d_out, int out_size) {
    const float* inputs = (const float*)d_in[0];
    const float* W1  = (const float*)d_in[1];
    const float* b1  = (const float*)d_in[2];
    const float* W2  = (const float*)d_in[3];
    const float* b2  = (const float*)d_in[4];
    const float* W3  = (const float*)d_in[5];
    const float* b3  = (const float*)d_in[6];
    const float* w01 = (const float*)d_in[7];
    const float* b01 = (const float*)d_in[8];
    const float* w02 = (const float*)d_in[9];
    const float* b02 = (const float*)d_in[10];
    const float* w03 = (const float*)d_in[11];
    const float* b03 = (const float*)d_in[12];
    float* out = (float*)d_out;

    prep_kernel<<<NMLP, THREADS>>>(W1, W2, w01, b01, w02, b02, w03, b03);

    cudaFuncSetAttribute(mlplist_kernel,
                         cudaFuncAttributeMaxDynamicSharedMemorySize, SMEM_BYTES);
    mlplist_kernel<<<NTILES, THREADS, SMEM_BYTES>>>(
        inputs, b1, b2, W3, b3, out);
}